// round 1
// baseline (speedup 1.0000x reference)
#include <cuda_runtime.h>
#include <math.h>

#define MAXN 512
#define KWAVE 8

// ---------------- device globals (no allocation allowed) ----------------
__device__ float4 g_cull [MAXN];   // px, py, r2(cull), opacity
__device__ float4 g_full1[MAXN];   // conA, conB, conC, a2x
__device__ float4 g_full2[MAXN];   // a2y, colR, colG, colB
__device__ float4 g_wc0  [MAXN];   // wave coeffs 0..3
__device__ float4 g_wc1  [MAXN];   // wave coeffs 4..7
__device__ float4 g_wo0  [MAXN];   // omega 0..3  (2*pi*freq/W folded)
__device__ float4 g_wo1  [MAXN];   // omega 4..7
__device__ int    g_order[MAXN];   // depth-sorted primitive indices

// ---------------- preprocess + bitonic depth sort ----------------
__global__ void prep_kernel(const float* __restrict__ colors,
                            const float* __restrict__ opac,
                            const float* __restrict__ pos,
                            const float* __restrict__ scales,
                            const float* __restrict__ rots,
                            const float* __restrict__ wcoef,
                            const int*   __restrict__ widx,
                            const float* __restrict__ view,
                            const float* __restrict__ VP,
                            int N, float fx, float fy, float Wf, float Hf)
{
    __shared__ float sk[MAXN];
    __shared__ int   sv[MAXN];

    int i = threadIdx.x;
    float depth = 3.0e38f;

    if (i < N) {
        // quaternion -> rotation
        float q0 = rots[4*i+0], q1 = rots[4*i+1], q2 = rots[4*i+2], q3 = rots[4*i+3];
        float qn = sqrtf(q0*q0 + q1*q1 + q2*q2 + q3*q3) + 1e-8f;
        float r = q0/qn, x = q1/qn, y = q2/qn, z = q3/qn;
        float R00 = 1.f - 2.f*(y*y + z*z), R01 = 2.f*(x*y - r*z), R02 = 2.f*(x*z + r*y);
        float R10 = 2.f*(x*y + r*z), R11 = 1.f - 2.f*(x*x + z*z), R12 = 2.f*(y*z - r*x);
        float R20 = 2.f*(x*z - r*y), R21 = 2.f*(y*z + r*x), R22 = 1.f - 2.f*(x*x + y*y);

        float sx = expf(scales[3*i+0]); float sy = expf(scales[3*i+1]); float sz = expf(scales[3*i+2]);
        float s0 = sx*sx, s1 = sy*sy, s2 = sz*sz;

        // Sigma = R diag(s^2) R^T (symmetric)
        float S00 = R00*R00*s0 + R01*R01*s1 + R02*R02*s2;
        float S01 = R00*R10*s0 + R01*R11*s1 + R02*R12*s2;
        float S02 = R00*R20*s0 + R01*R21*s1 + R02*R22*s2;
        float S11 = R10*R10*s0 + R11*R11*s1 + R12*R12*s2;
        float S12 = R10*R20*s0 + R11*R21*s1 + R12*R22*s2;
        float S22 = R20*R20*s0 + R21*R21*s1 + R22*R22*s2;

        float p0 = pos[3*i+0], p1 = pos[3*i+1], p2 = pos[3*i+2];

        float tx  = view[0]*p0 + view[1]*p1 + view[2]*p2  + view[3];
        float ty  = view[4]*p0 + view[5]*p1 + view[6]*p2  + view[7];
        float tzc = view[8]*p0 + view[9]*p1 + view[10]*p2 + view[11];

        float c0 = VP[0]*p0  + VP[1]*p1  + VP[2]*p2  + VP[3];
        float c1 = VP[4]*p0  + VP[5]*p1  + VP[6]*p2  + VP[7];
        float w  = VP[12]*p0 + VP[13]*p1 + VP[14]*p2 + VP[15];
        float wsafe = (fabsf(w) > 1e-6f) ? w : 1e-6f;
        float pxx = (c0/wsafe * 0.5f + 0.5f) * Wf;
        float pyy = (c1/wsafe * 0.5f + 0.5f) * Hf;

        depth = tzc;
        float tzm = fmaxf(depth, 0.1f);
        float inv = 1.0f / tzm;
        float J00 = fx*inv, J02 = -fx*tx*inv*inv;
        float J11 = fy*inv, J12 = -fy*ty*inv*inv;

        // M = J * view[:3,:3]
        float M00 = J00*view[0] + J02*view[8];
        float M01 = J00*view[1] + J02*view[9];
        float M02 = J00*view[2] + J02*view[10];
        float M10 = J11*view[4] + J12*view[8];
        float M11 = J11*view[5] + J12*view[9];
        float M12 = J11*view[6] + J12*view[10];

        // cov2d = M Sigma M^T
        float t00 = M00*S00 + M01*S01 + M02*S02;
        float t01 = M00*S01 + M01*S11 + M02*S12;
        float t02 = M00*S02 + M01*S12 + M02*S22;
        float t10 = M10*S00 + M11*S01 + M12*S02;
        float t11 = M10*S01 + M11*S11 + M12*S12;
        float t12 = M10*S02 + M11*S12 + M12*S22;
        float cov00 = t00*M00 + t01*M01 + t02*M02;
        float cov01 = t00*M10 + t01*M11 + t02*M12;
        float cov11 = t10*M10 + t11*M11 + t12*M12;

        float A = cov00 + 0.3f, B = cov01, C = cov11 + 0.3f;
        float det = fmaxf(A*C - B*B, 1e-12f);
        float invd = 1.0f / det;
        float conA = C*invd, conB = -B*invd, conC = A*invd;

        // a2 = normalize(M * R[:,0])
        float a2x = M00*R00 + M01*R10 + M02*R20;
        float a2y = M10*R00 + M11*R10 + M12*R20;
        float an = sqrtf(a2x*a2x + a2y*a2y) + 1e-8f;
        a2x /= an; a2y /= an;

        float op = opac[i];

        float cc[KWAVE], om[KWAVE];
        float maxw = 0.f;
        #pragma unroll
        for (int k = 0; k < KWAVE; k++) {
            cc[k] = wcoef[KWAVE*i + k];
            // 2*pi * idx * (128/1024) / W  = (pi/4) * idx / W
            om[k] = 0.785398163397448f * (float)widx[KWAVE*i + k] / Wf;
            maxw += fabsf(cc[k]);
        }

        bool valid = (depth > 0.1f) && (w > 1e-4f);

        // conservative cull radius: alpha <= op*maxw*exp(-0.5*lmin*d^2) < 1e-8 outside r2
        float mean = 0.5f*(conA + conC);
        float lmin = mean - sqrtf(fmaxf(0.25f*(conA-conC)*(conA-conC) + conB*conB, 0.f));
        lmin = fmaxf(lmin, 1e-12f);
        float r2 = 0.f;
        float prod = op * maxw;
        if (valid && prod > 0.f) {
            float thr = logf(prod) + 18.4207f;   // ln(1e8)
            if (thr > 0.f) r2 = 2.f * thr / lmin;
        }

        g_cull [i] = make_float4(pxx, pyy, r2, op);
        g_full1[i] = make_float4(conA, conB, conC, a2x);
        g_full2[i] = make_float4(a2y, colors[3*i+0], colors[3*i+1], colors[3*i+2]);
        g_wc0  [i] = make_float4(cc[0], cc[1], cc[2], cc[3]);
        g_wc1  [i] = make_float4(cc[4], cc[5], cc[6], cc[7]);
        g_wo0  [i] = make_float4(om[0], om[1], om[2], om[3]);
        g_wo1  [i] = make_float4(om[4], om[5], om[6], om[7]);
    }

    // bitonic sort (depth, idx) over 512 slots
    sk[i] = depth;
    sv[i] = i;
    __syncthreads();
    for (int k = 2; k <= MAXN; k <<= 1) {
        for (int j = k >> 1; j > 0; j >>= 1) {
            int ixj = i ^ j;
            if (ixj > i) {
                bool up = ((i & k) == 0);
                float ka = sk[i], kb = sk[ixj];
                if ((ka > kb) == up) {
                    sk[i] = kb; sk[ixj] = ka;
                    int va = sv[i]; sv[i] = sv[ixj]; sv[ixj] = va;
                }
            }
            __syncthreads();
        }
    }
    g_order[i] = sv[i];
}

// ---------------- render: 16x8 pixel tiles, 512-prim sorted loop ----------------
__global__ void __launch_bounds__(128) render_kernel(const float* __restrict__ bg,
                                                     float* __restrict__ out,
                                                     int N, int W, int H)
{
    __shared__ float4 sh_cull[MAXN];
    __shared__ int    sh_ord [MAXN];

    int tid  = threadIdx.y * blockDim.x + threadIdx.x;
    int nthr = blockDim.x * blockDim.y;
    for (int j = tid; j < N; j += nthr) {
        int o = g_order[j];
        sh_ord[j]  = o;
        sh_cull[j] = g_cull[o];
    }
    __syncthreads();

    int x = blockIdx.x * blockDim.x + threadIdx.x;
    int y = blockIdx.y * blockDim.y + threadIdx.y;
    float gx = (float)x + 0.5f;
    float gy = (float)y + 0.5f;

    float T = 1.0f, cr = 0.f, cg = 0.f, cb = 0.f;

    for (int j = 0; j < N; j++) {
        float4 c = sh_cull[j];
        float dx = c.x - gx;
        float dy = c.y - gy;
        float d2 = dx*dx + dy*dy;
        if (d2 < c.z) {
            int o = sh_ord[j];
            float4 f1 = g_full1[o];
            float4 f2 = g_full2[o];
            float power = -0.5f*(f1.x*dx*dx + f1.z*dy*dy) - f1.y*dx*dy;
            float G = __expf(fminf(power, 0.f));
            float t = dx*f1.w + dy*f2.x;
            float4 wc0 = g_wc0[o], wc1 = g_wc1[o];
            float4 wo0 = g_wo0[o], wo1 = g_wo1[o];
            float wave = wc0.x*__cosf(wo0.x*t) + wc0.y*__cosf(wo0.y*t)
                       + wc0.z*__cosf(wo0.z*t) + wc0.w*__cosf(wo0.w*t)
                       + wc1.x*__cosf(wo1.x*t) + wc1.y*__cosf(wo1.y*t)
                       + wc1.z*__cosf(wo1.z*t) + wc1.w*__cosf(wo1.w*t);
            float alpha = fminf(fmaxf(c.w * G * wave, 0.f), 0.99f);
            float wgt = alpha * T;
            cr += wgt * f2.y;
            cg += wgt * f2.z;
            cb += wgt * f2.w;
            T *= 1.0f - alpha;
        }
    }

    if (x < W && y < H) {
        int pix = y*W + x;
        int HW = W*H;
        out[pix]        = cr + bg[0]*T;
        out[HW + pix]   = cg + bg[1]*T;
        out[2*HW + pix] = cb + bg[2]*T;
    }
}

// ---------------- launch ----------------
extern "C" void kernel_launch(void* const* d_in, const int* in_sizes, int n_in,
                              void* d_out, int out_size)
{
    const float* colors = (const float*)d_in[0];
    const float* opac   = (const float*)d_in[1];
    const float* bg     = (const float*)d_in[2];
    const float* pos    = (const float*)d_in[3];
    const float* scales = (const float*)d_in[4];
    const float* rots   = (const float*)d_in[5];
    const float* wcoef  = (const float*)d_in[6];
    const int*   widx   = (const int*)d_in[7];
    const float* view   = (const float*)d_in[9];
    const float* VP     = (const float*)d_in[10];

    int N = in_sizes[3] / 3;
    if (N > MAXN) N = MAXN;

    int HW = out_size / 3;
    int W = 200, H = 200;
    if (HW != 40000) {
        W = (int)(sqrt((double)HW) + 0.5);
        H = (W > 0) ? HW / W : 0;
    }

    const double tanx = tan(30.0 * M_PI / 180.0);  // FOV 60 deg
    const double tany = tan(30.0 * M_PI / 180.0);
    float fx = (float)(W / (2.0 * tanx));
    float fy = (float)(H / (2.0 * tany));

    prep_kernel<<<1, MAXN>>>(colors, opac, pos, scales, rots, wcoef, widx,
                             view, VP, N, fx, fy, (float)W, (float)H);

    dim3 blk(16, 8);
    dim3 grd((W + blk.x - 1) / blk.x, (H + blk.y - 1) / blk.y);
    render_kernel<<<grd, blk>>>(bg, (float*)d_out, N, W, H);
}

// round 2
// speedup vs baseline: 2.0374x; 2.0374x over previous
#include <cuda_runtime.h>
#include <math.h>

#define MAXN 512
#define KWAVE 8
#define NCHUNK 4   // MAXN / 128

// ---------------- device globals (no allocation allowed) ----------------
__device__ float4 g_cull [MAXN];   // px, py, r2(cull), opacity
__device__ float4 g_full1[MAXN];   // conA, conB, conC, a2x
__device__ float4 g_full2[MAXN];   // a2y, colR, colG, colB
__device__ float4 g_wc0  [MAXN];   // wave coeffs 0..3
__device__ float4 g_wc1  [MAXN];   // wave coeffs 4..7
__device__ float4 g_wo0  [MAXN];   // omega 0..3  (2*pi*freq/W folded)
__device__ float4 g_wo1  [MAXN];   // omega 4..7
__device__ int    g_order[MAXN];   // depth-sorted primitive indices

// ---------------- preprocess + bitonic depth sort ----------------
__global__ void prep_kernel(const float* __restrict__ colors,
                            const float* __restrict__ opac,
                            const float* __restrict__ pos,
                            const float* __restrict__ scales,
                            const float* __restrict__ rots,
                            const float* __restrict__ wcoef,
                            const int*   __restrict__ widx,
                            const float* __restrict__ view,
                            const float* __restrict__ VP,
                            int N, float fx, float fy, float Wf, float Hf)
{
    __shared__ float sk[MAXN];
    __shared__ int   sv[MAXN];

    int i = threadIdx.x;
    float depth = 3.0e38f;

    if (i < N) {
        // quaternion -> rotation
        float q0 = rots[4*i+0], q1 = rots[4*i+1], q2 = rots[4*i+2], q3 = rots[4*i+3];
        float qn = sqrtf(q0*q0 + q1*q1 + q2*q2 + q3*q3) + 1e-8f;
        float r = q0/qn, x = q1/qn, y = q2/qn, z = q3/qn;
        float R00 = 1.f - 2.f*(y*y + z*z), R01 = 2.f*(x*y - r*z), R02 = 2.f*(x*z + r*y);
        float R10 = 2.f*(x*y + r*z), R11 = 1.f - 2.f*(x*x + z*z), R12 = 2.f*(y*z - r*x);
        float R20 = 2.f*(x*z - r*y), R21 = 2.f*(y*z + r*x), R22 = 1.f - 2.f*(x*x + y*y);

        float sx = expf(scales[3*i+0]); float sy = expf(scales[3*i+1]); float sz = expf(scales[3*i+2]);
        float s0 = sx*sx, s1 = sy*sy, s2 = sz*sz;

        // Sigma = R diag(s^2) R^T (symmetric)
        float S00 = R00*R00*s0 + R01*R01*s1 + R02*R02*s2;
        float S01 = R00*R10*s0 + R01*R11*s1 + R02*R12*s2;
        float S02 = R00*R20*s0 + R01*R21*s1 + R02*R22*s2;
        float S11 = R10*R10*s0 + R11*R11*s1 + R12*R12*s2;
        float S12 = R10*R20*s0 + R11*R21*s1 + R12*R22*s2;
        float S22 = R20*R20*s0 + R21*R21*s1 + R22*R22*s2;

        float p0 = pos[3*i+0], p1 = pos[3*i+1], p2 = pos[3*i+2];

        float tx  = view[0]*p0 + view[1]*p1 + view[2]*p2  + view[3];
        float ty  = view[4]*p0 + view[5]*p1 + view[6]*p2  + view[7];
        float tzc = view[8]*p0 + view[9]*p1 + view[10]*p2 + view[11];

        float c0 = VP[0]*p0  + VP[1]*p1  + VP[2]*p2  + VP[3];
        float c1 = VP[4]*p0  + VP[5]*p1  + VP[6]*p2  + VP[7];
        float w  = VP[12]*p0 + VP[13]*p1 + VP[14]*p2 + VP[15];
        float wsafe = (fabsf(w) > 1e-6f) ? w : 1e-6f;
        float pxx = (c0/wsafe * 0.5f + 0.5f) * Wf;
        float pyy = (c1/wsafe * 0.5f + 0.5f) * Hf;

        depth = tzc;
        float tzm = fmaxf(depth, 0.1f);
        float inv = 1.0f / tzm;
        float J00 = fx*inv, J02 = -fx*tx*inv*inv;
        float J11 = fy*inv, J12 = -fy*ty*inv*inv;

        // M = J * view[:3,:3]
        float M00 = J00*view[0] + J02*view[8];
        float M01 = J00*view[1] + J02*view[9];
        float M02 = J00*view[2] + J02*view[10];
        float M10 = J11*view[4] + J12*view[8];
        float M11 = J11*view[5] + J12*view[9];
        float M12 = J11*view[6] + J12*view[10];

        // cov2d = M Sigma M^T
        float t00 = M00*S00 + M01*S01 + M02*S02;
        float t01 = M00*S01 + M01*S11 + M02*S12;
        float t02 = M00*S02 + M01*S12 + M02*S22;
        float t10 = M10*S00 + M11*S01 + M12*S02;
        float t11 = M10*S01 + M11*S11 + M12*S12;
        float t12 = M10*S02 + M11*S12 + M12*S22;
        float cov00 = t00*M00 + t01*M01 + t02*M02;
        float cov01 = t00*M10 + t01*M11 + t02*M12;
        float cov11 = t10*M10 + t11*M11 + t12*M12;

        float A = cov00 + 0.3f, B = cov01, C = cov11 + 0.3f;
        float det = fmaxf(A*C - B*B, 1e-12f);
        float invd = 1.0f / det;
        float conA = C*invd, conB = -B*invd, conC = A*invd;

        // a2 = normalize(M * R[:,0])
        float a2x = M00*R00 + M01*R10 + M02*R20;
        float a2y = M10*R00 + M11*R10 + M12*R20;
        float an = sqrtf(a2x*a2x + a2y*a2y) + 1e-8f;
        a2x /= an; a2y /= an;

        float op = opac[i];

        float cc[KWAVE], om[KWAVE];
        float maxw = 0.f;
        #pragma unroll
        for (int k = 0; k < KWAVE; k++) {
            cc[k] = wcoef[KWAVE*i + k];
            // 2*pi * idx * (128/1024) / W  = (pi/4) * idx / W
            om[k] = 0.785398163397448f * (float)widx[KWAVE*i + k] / Wf;
            maxw += fabsf(cc[k]);
        }

        bool valid = (depth > 0.1f) && (w > 1e-4f);

        // conservative cull radius: alpha <= op*maxw*exp(-0.5*lmin*d^2) < 1e-8 outside r2
        float mean = 0.5f*(conA + conC);
        float lmin = mean - sqrtf(fmaxf(0.25f*(conA-conC)*(conA-conC) + conB*conB, 0.f));
        lmin = fmaxf(lmin, 1e-12f);
        float r2 = 0.f;
        float prod = op * maxw;
        if (valid && prod > 0.f) {
            float thr = logf(prod) + 18.4207f;   // ln(1e8)
            if (thr > 0.f) r2 = 2.f * thr / lmin;
        }

        g_cull [i] = make_float4(pxx, pyy, r2, op);
        g_full1[i] = make_float4(conA, conB, conC, a2x);
        g_full2[i] = make_float4(a2y, colors[3*i+0], colors[3*i+1], colors[3*i+2]);
        g_wc0  [i] = make_float4(cc[0], cc[1], cc[2], cc[3]);
        g_wc1  [i] = make_float4(cc[4], cc[5], cc[6], cc[7]);
        g_wo0  [i] = make_float4(om[0], om[1], om[2], om[3]);
        g_wo1  [i] = make_float4(om[4], om[5], om[6], om[7]);
    }

    // bitonic sort (depth, idx) over 512 slots
    sk[i] = depth;
    sv[i] = i;
    __syncthreads();
    for (int k = 2; k <= MAXN; k <<= 1) {
        for (int j = k >> 1; j > 0; j >>= 1) {
            int ixj = i ^ j;
            if (ixj > i) {
                bool up = ((i & k) == 0);
                float ka = sk[i], kb = sk[ixj];
                if ((ka > kb) == up) {
                    sk[i] = kb; sk[ixj] = ka;
                    int va = sv[i]; sv[i] = sv[ixj]; sv[ixj] = va;
                }
            }
            __syncthreads();
        }
    }
    g_order[i] = sv[i];
}

// ---------------- render: 16x8 tiles + order-preserving tile cull ----------------
__global__ void __launch_bounds__(128) render_kernel(const float* __restrict__ bg,
                                                     float* __restrict__ out,
                                                     int N, int W, int H)
{
    __shared__ float4 s_rec[MAXN];     // compacted cull records (depth order)
    __shared__ int    s_ord[MAXN];     // compacted primitive ids
    __shared__ int    s_cnt[NCHUNK*4]; // per (chunk, warp) pass counts
    __shared__ int    s_total;

    int tid  = threadIdx.y * blockDim.x + threadIdx.x;
    int warp = tid >> 5;
    int lane = tid & 31;

    // tile bounds (pixel centers)
    float xmin = (float)(blockIdx.x * 16) + 0.5f;
    float ymin = (float)(blockIdx.y * 8)  + 0.5f;
    float xmax = xmin + 15.0f;
    float ymax = ymin + 7.0f;

    // ---- phase 1: parallel tile cull, order-preserving compaction ----
    float4   rec[NCHUNK];
    int      ord[NCHUNK];
    bool     pass[NCHUNK];
    unsigned msk[NCHUNK];

    #pragma unroll
    for (int c = 0; c < NCHUNK; c++) {
        int j = c * 128 + tid;
        bool p = false;
        float4 r = make_float4(0.f, 0.f, 0.f, 0.f);
        int o = 0;
        if (j < N) {
            o = g_order[j];
            r = g_cull[o];
            float nx = fminf(fmaxf(r.x, xmin), xmax);
            float ny = fminf(fmaxf(r.y, ymin), ymax);
            float ddx = r.x - nx, ddy = r.y - ny;
            p = (ddx*ddx + ddy*ddy) < r.z;
        }
        rec[c] = r; ord[c] = o; pass[c] = p;
        msk[c] = __ballot_sync(0xffffffffu, p);
        if (lane == 0) s_cnt[c*4 + warp] = __popc(msk[c]);
    }
    __syncthreads();

    int pre[NCHUNK];
    {
        int cnts[NCHUNK*4];
        #pragma unroll
        for (int k = 0; k < NCHUNK*4; k++) cnts[k] = s_cnt[k];
        int run = 0;
        #pragma unroll
        for (int c = 0; c < NCHUNK; c++) {
            pre[c] = run;
            #pragma unroll
            for (int wv = 0; wv < 4; wv++) {
                if (wv < warp) pre[c] += cnts[c*4 + wv];
                run += cnts[c*4 + wv];
            }
        }
        if (tid == 0) s_total = run;
    }
    #pragma unroll
    for (int c = 0; c < NCHUNK; c++) {
        if (pass[c]) {
            int off = pre[c] + __popc(msk[c] & ((1u << lane) - 1));
            s_rec[off] = rec[c];
            s_ord[off] = ord[c];
        }
    }
    __syncthreads();
    int M = s_total;

    // ---- phase 2: per-pixel composite over compacted list ----
    int x = blockIdx.x * 16 + threadIdx.x;
    int y = blockIdx.y * 8  + threadIdx.y;
    float gx = (float)x + 0.5f;
    float gy = (float)y + 0.5f;

    float T = 1.0f, cr = 0.f, cg = 0.f, cb = 0.f;

    for (int m = 0; m < M; m++) {
        float4 c = s_rec[m];
        float dx = c.x - gx;
        float dy = c.y - gy;
        float d2 = dx*dx + dy*dy;
        if (d2 < c.z) {
            int o = s_ord[m];
            float4 f1 = g_full1[o];
            float4 f2 = g_full2[o];
            float power = -0.5f*(f1.x*dx*dx + f1.z*dy*dy) - f1.y*dx*dy;
            float G = __expf(fminf(power, 0.f));
            float t = dx*f1.w + dy*f2.x;
            float4 wc0 = g_wc0[o], wc1 = g_wc1[o];
            float4 wo0 = g_wo0[o], wo1 = g_wo1[o];
            float wave = wc0.x*__cosf(wo0.x*t) + wc0.y*__cosf(wo0.y*t)
                       + wc0.z*__cosf(wo0.z*t) + wc0.w*__cosf(wo0.w*t)
                       + wc1.x*__cosf(wo1.x*t) + wc1.y*__cosf(wo1.y*t)
                       + wc1.z*__cosf(wo1.z*t) + wc1.w*__cosf(wo1.w*t);
            float alpha = fminf(fmaxf(c.w * G * wave, 0.f), 0.99f);
            float wgt = alpha * T;
            cr += wgt * f2.y;
            cg += wgt * f2.z;
            cb += wgt * f2.w;
            T *= 1.0f - alpha;
        }
    }

    if (x < W && y < H) {
        int pix = y*W + x;
        int HW = W*H;
        out[pix]        = cr + bg[0]*T;
        out[HW + pix]   = cg + bg[1]*T;
        out[2*HW + pix] = cb + bg[2]*T;
    }
}

// ---------------- launch ----------------
extern "C" void kernel_launch(void* const* d_in, const int* in_sizes, int n_in,
                              void* d_out, int out_size)
{
    const float* colors = (const float*)d_in[0];
    const float* opac   = (const float*)d_in[1];
    const float* bg     = (const float*)d_in[2];
    const float* pos    = (const float*)d_in[3];
    const float* scales = (const float*)d_in[4];
    const float* rots   = (const float*)d_in[5];
    const float* wcoef  = (const float*)d_in[6];
    const int*   widx   = (const int*)d_in[7];
    const float* view   = (const float*)d_in[9];
    const float* VP     = (const float*)d_in[10];

    int N = in_sizes[3] / 3;
    if (N > MAXN) N = MAXN;

    int HW = out_size / 3;
    int W = 200, H = 200;
    if (HW != 40000) {
        W = (int)(sqrt((double)HW) + 0.5);
        H = (W > 0) ? HW / W : 0;
    }

    const double tanx = tan(30.0 * M_PI / 180.0);  // FOV 60 deg
    const double tany = tan(30.0 * M_PI / 180.0);
    float fx = (float)(W / (2.0 * tanx));
    float fy = (float)(H / (2.0 * tany));

    prep_kernel<<<1, MAXN>>>(colors, opac, pos, scales, rots, wcoef, widx,
                             view, VP, N, fx, fy, (float)W, (float)H);

    dim3 blk(16, 8);
    dim3 grd((W + blk.x - 1) / blk.x, (H + blk.y - 1) / blk.y);
    render_kernel<<<grd, blk>>>(bg, (float*)d_out, N, W, H);
}

// round 3
// speedup vs baseline: 2.9033x; 1.4250x over previous
#include <cuda_runtime.h>
#include <math.h>

#define MAXN 512
#define KWAVE 8

// ---------------- device globals (no allocation allowed) ----------------
__device__ float4 g_cull [MAXN];   // px, py, r2(cull), opacity
__device__ float4 g_full1[MAXN];   // conA, conB, conC, a2x
__device__ float4 g_full2[MAXN];   // a2y, colR, colG, colB
__device__ float4 g_wc0  [MAXN];   // wave coeffs 0..3
__device__ float4 g_wc1  [MAXN];   // wave coeffs 4..7
__device__ float4 g_wo0  [MAXN];   // omega 0..3  (2*pi*freq/W folded)
__device__ float4 g_wo1  [MAXN];   // omega 4..7
__device__ int    g_order[MAXN];   // depth-sorted primitive indices

// ---------------- preprocess + hybrid bitonic depth sort ----------------
__global__ void prep_kernel(const float* __restrict__ colors,
                            const float* __restrict__ opac,
                            const float* __restrict__ pos,
                            const float* __restrict__ scales,
                            const float* __restrict__ rots,
                            const float* __restrict__ wcoef,
                            const int*   __restrict__ widx,
                            const float* __restrict__ view,
                            const float* __restrict__ VP,
                            int N, float fx, float fy, float Wf, float Hf)
{
    __shared__ float sk[MAXN];
    __shared__ int   sv[MAXN];

    int i = threadIdx.x;
    float depth = 3.0e38f;

    if (i < N) {
        // quaternion -> rotation
        float q0 = rots[4*i+0], q1 = rots[4*i+1], q2 = rots[4*i+2], q3 = rots[4*i+3];
        float qn = sqrtf(q0*q0 + q1*q1 + q2*q2 + q3*q3) + 1e-8f;
        float r = q0/qn, x = q1/qn, y = q2/qn, z = q3/qn;
        float R00 = 1.f - 2.f*(y*y + z*z), R01 = 2.f*(x*y - r*z), R02 = 2.f*(x*z + r*y);
        float R10 = 2.f*(x*y + r*z), R11 = 1.f - 2.f*(x*x + z*z), R12 = 2.f*(y*z - r*x);
        float R20 = 2.f*(x*z - r*y), R21 = 2.f*(y*z + r*x), R22 = 1.f - 2.f*(x*x + y*y);

        float sx = expf(scales[3*i+0]); float sy = expf(scales[3*i+1]); float sz = expf(scales[3*i+2]);
        float s0 = sx*sx, s1 = sy*sy, s2 = sz*sz;

        float S00 = R00*R00*s0 + R01*R01*s1 + R02*R02*s2;
        float S01 = R00*R10*s0 + R01*R11*s1 + R02*R12*s2;
        float S02 = R00*R20*s0 + R01*R21*s1 + R02*R22*s2;
        float S11 = R10*R10*s0 + R11*R11*s1 + R12*R12*s2;
        float S12 = R10*R20*s0 + R11*R21*s1 + R12*R22*s2;
        float S22 = R20*R20*s0 + R21*R21*s1 + R22*R22*s2;

        float p0 = pos[3*i+0], p1 = pos[3*i+1], p2 = pos[3*i+2];

        float tx  = view[0]*p0 + view[1]*p1 + view[2]*p2  + view[3];
        float ty  = view[4]*p0 + view[5]*p1 + view[6]*p2  + view[7];
        float tzc = view[8]*p0 + view[9]*p1 + view[10]*p2 + view[11];

        float c0 = VP[0]*p0  + VP[1]*p1  + VP[2]*p2  + VP[3];
        float c1 = VP[4]*p0  + VP[5]*p1  + VP[6]*p2  + VP[7];
        float w  = VP[12]*p0 + VP[13]*p1 + VP[14]*p2 + VP[15];
        float wsafe = (fabsf(w) > 1e-6f) ? w : 1e-6f;
        float pxx = (c0/wsafe * 0.5f + 0.5f) * Wf;
        float pyy = (c1/wsafe * 0.5f + 0.5f) * Hf;

        depth = tzc;
        float tzm = fmaxf(depth, 0.1f);
        float inv = 1.0f / tzm;
        float J00 = fx*inv, J02 = -fx*tx*inv*inv;
        float J11 = fy*inv, J12 = -fy*ty*inv*inv;

        float M00 = J00*view[0] + J02*view[8];
        float M01 = J00*view[1] + J02*view[9];
        float M02 = J00*view[2] + J02*view[10];
        float M10 = J11*view[4] + J12*view[8];
        float M11 = J11*view[5] + J12*view[9];
        float M12 = J11*view[6] + J12*view[10];

        float t00 = M00*S00 + M01*S01 + M02*S02;
        float t01 = M00*S01 + M01*S11 + M02*S12;
        float t02 = M00*S02 + M01*S12 + M02*S22;
        float t10 = M10*S00 + M11*S01 + M12*S02;
        float t11 = M10*S01 + M11*S11 + M12*S12;
        float t12 = M10*S02 + M11*S12 + M12*S22;
        float cov00 = t00*M00 + t01*M01 + t02*M02;
        float cov01 = t00*M10 + t01*M11 + t02*M12;
        float cov11 = t10*M10 + t11*M11 + t12*M12;

        float A = cov00 + 0.3f, B = cov01, C = cov11 + 0.3f;
        float det = fmaxf(A*C - B*B, 1e-12f);
        float invd = 1.0f / det;
        float conA = C*invd, conB = -B*invd, conC = A*invd;

        float a2x = M00*R00 + M01*R10 + M02*R20;
        float a2y = M10*R00 + M11*R10 + M12*R20;
        float an = sqrtf(a2x*a2x + a2y*a2y) + 1e-8f;
        a2x /= an; a2y /= an;

        float op = opac[i];

        float cc[KWAVE], om[KWAVE];
        float maxw = 0.f;
        #pragma unroll
        for (int k = 0; k < KWAVE; k++) {
            cc[k] = wcoef[KWAVE*i + k];
            om[k] = 0.785398163397448f * (float)widx[KWAVE*i + k] / Wf;
            maxw += fabsf(cc[k]);
        }

        bool valid = (depth > 0.1f) && (w > 1e-4f);

        float mean = 0.5f*(conA + conC);
        float lmin = mean - sqrtf(fmaxf(0.25f*(conA-conC)*(conA-conC) + conB*conB, 0.f));
        lmin = fmaxf(lmin, 1e-12f);
        float r2 = 0.f;
        float prod = op * maxw;
        if (valid && prod > 0.f) {
            float thr = logf(prod) + 18.4207f;   // ln(1e8)
            if (thr > 0.f) r2 = 2.f * thr / lmin;
        }

        g_cull [i] = make_float4(pxx, pyy, r2, op);
        g_full1[i] = make_float4(conA, conB, conC, a2x);
        g_full2[i] = make_float4(a2y, colors[3*i+0], colors[3*i+1], colors[3*i+2]);
        g_wc0  [i] = make_float4(cc[0], cc[1], cc[2], cc[3]);
        g_wc1  [i] = make_float4(cc[4], cc[5], cc[6], cc[7]);
        g_wo0  [i] = make_float4(om[0], om[1], om[2], om[3]);
        g_wo1  [i] = make_float4(om[4], om[5], om[6], om[7]);
    }

    // hybrid bitonic sort: cross-warp (j>=32) via shared, intra-warp via shfl
    float key = depth;
    int   val = i;
    #pragma unroll
    for (int k = 2; k <= MAXN; k <<= 1) {
        bool up = ((i & k) == 0);
        #pragma unroll
        for (int j = k >> 1; j > 0; j >>= 1) {
            float okey; int oval;
            if (j >= 32) {
                sk[i] = key; sv[i] = val;
                __syncthreads();
                okey = sk[i ^ j]; oval = sv[i ^ j];
                __syncthreads();
            } else {
                okey = __shfl_xor_sync(0xffffffffu, key, j);
                oval = __shfl_xor_sync(0xffffffffu, val, j);
            }
            bool lower  = ((i & j) == 0);
            bool takeMin = (lower == up);
            bool sw = takeMin ? (okey < key) : (okey > key);
            if (sw) { key = okey; val = oval; }
        }
    }
    g_order[i] = val;
}

// ---------------- render: 16x8 tiles, 4 depth-segment layers ----------------
__global__ void __launch_bounds__(512) render_kernel(const float* __restrict__ bg,
                                                     float* __restrict__ out,
                                                     int N, int W, int H)
{
    __shared__ float4 s_rec[MAXN];   // px,py,r2,op (depth order, compacted)
    __shared__ float4 s_f1 [MAXN];   // conA,conB,conC,a2x
    __shared__ float4 s_f2 [MAXN];   // a2y,colR,colG,colB
    __shared__ int    s_ord[MAXN];
    __shared__ int    s_cnt[16];
    __shared__ int    s_total;
    __shared__ float4 s_acc[4][128]; // per-segment (cr,cg,cb,T)

    int tid  = (threadIdx.z * 8 + threadIdx.y) * 16 + threadIdx.x;
    int warp = tid >> 5;
    int lane = tid & 31;

    // tile bounds (pixel centers)
    float xmin = (float)(blockIdx.x * 16) + 0.5f;
    float ymin = (float)(blockIdx.y * 8)  + 0.5f;
    float xmax = xmin + 15.0f;
    float ymax = ymin + 7.0f;

    // ---- phase 1: tile cull (one prim per thread), order-preserving compact ----
    bool p = false;
    float4 r = make_float4(0.f, 0.f, 0.f, 0.f);
    int o = 0;
    if (tid < N) {
        o = g_order[tid];
        r = g_cull[o];
        float nx = fminf(fmaxf(r.x, xmin), xmax);
        float ny = fminf(fmaxf(r.y, ymin), ymax);
        float ddx = r.x - nx, ddy = r.y - ny;
        p = (ddx*ddx + ddy*ddy) < r.z;
    }
    unsigned msk = __ballot_sync(0xffffffffu, p);
    if (lane == 0) s_cnt[warp] = __popc(msk);
    __syncthreads();

    int pre = 0, run = 0;
    {
        #pragma unroll
        for (int wv = 0; wv < 16; wv++) {
            int c = s_cnt[wv];
            if (wv < warp) pre += c;
            run += c;
        }
        if (tid == 0) s_total = run;
    }
    if (p) {
        int off = pre + __popc(msk & ((1u << lane) - 1));
        s_rec[off] = r;
        s_ord[off] = o;
        s_f1 [off] = g_full1[o];
        s_f2 [off] = g_full2[o];
    }
    __syncthreads();
    int M = s_total;

    // ---- phase 2: per-pixel composite, 4 depth segments in parallel ----
    int x = blockIdx.x * 16 + threadIdx.x;
    int y = blockIdx.y * 8  + threadIdx.y;
    int seg = threadIdx.z;
    float gx = (float)x + 0.5f;
    float gy = (float)y + 0.5f;

    int m0 = (M * seg)     >> 2;
    int m1 = (M * (seg+1)) >> 2;

    float T = 1.0f, cr = 0.f, cg = 0.f, cb = 0.f;

    for (int m = m0; m < m1; m++) {
        float4 c = s_rec[m];
        float dx = c.x - gx;
        float dy = c.y - gy;
        float d2 = dx*dx + dy*dy;
        if (d2 < c.z) {
            float4 f1 = s_f1[m];
            float4 f2 = s_f2[m];
            int oo = s_ord[m];
            float power = -0.5f*(f1.x*dx*dx + f1.z*dy*dy) - f1.y*dx*dy;
            float G = __expf(fminf(power, 0.f));
            float t = dx*f1.w + dy*f2.x;
            float4 wc0 = g_wc0[oo], wc1 = g_wc1[oo];
            float4 wo0 = g_wo0[oo], wo1 = g_wo1[oo];
            float wave = wc0.x*__cosf(wo0.x*t) + wc0.y*__cosf(wo0.y*t)
                       + wc0.z*__cosf(wo0.z*t) + wc0.w*__cosf(wo0.w*t)
                       + wc1.x*__cosf(wo1.x*t) + wc1.y*__cosf(wo1.y*t)
                       + wc1.z*__cosf(wo1.z*t) + wc1.w*__cosf(wo1.w*t);
            float alpha = fminf(fmaxf(c.w * G * wave, 0.f), 0.99f);
            float wgt = alpha * T;
            cr += wgt * f2.y;
            cg += wgt * f2.z;
            cb += wgt * f2.w;
            T *= 1.0f - alpha;
        }
    }

    int pixl = threadIdx.y * 16 + threadIdx.x;
    s_acc[seg][pixl] = make_float4(cr, cg, cb, T);
    __syncthreads();

    if (seg == 0 && x < W && y < H) {
        float4 a0 = s_acc[0][pixl];
        float4 a1 = s_acc[1][pixl];
        float4 a2 = s_acc[2][pixl];
        float4 a3 = s_acc[3][pixl];
        float fr = a0.x + a0.w*(a1.x + a1.w*(a2.x + a2.w*a3.x));
        float fg = a0.y + a0.w*(a1.y + a1.w*(a2.y + a2.w*a3.y));
        float fb = a0.z + a0.w*(a1.z + a1.w*(a2.z + a2.w*a3.z));
        float fT = a0.w * a1.w * a2.w * a3.w;
        int pix = y*W + x;
        int HW = W*H;
        out[pix]        = fr + bg[0]*fT;
        out[HW + pix]   = fg + bg[1]*fT;
        out[2*HW + pix] = fb + bg[2]*fT;
    }
}

// ---------------- launch ----------------
extern "C" void kernel_launch(void* const* d_in, const int* in_sizes, int n_in,
                              void* d_out, int out_size)
{
    const float* colors = (const float*)d_in[0];
    const float* opac   = (const float*)d_in[1];
    const float* bg     = (const float*)d_in[2];
    const float* pos    = (const float*)d_in[3];
    const float* scales = (const float*)d_in[4];
    const float* rots   = (const float*)d_in[5];
    const float* wcoef  = (const float*)d_in[6];
    const int*   widx   = (const int*)d_in[7];
    const float* view   = (const float*)d_in[9];
    const float* VP     = (const float*)d_in[10];

    int N = in_sizes[3] / 3;
    if (N > MAXN) N = MAXN;

    int HW = out_size / 3;
    int W = 200, H = 200;
    if (HW != 40000) {
        W = (int)(sqrt((double)HW) + 0.5);
        H = (W > 0) ? HW / W : 0;
    }

    const double tanx = tan(30.0 * M_PI / 180.0);  // FOV 60 deg
    const double tany = tan(30.0 * M_PI / 180.0);
    float fx = (float)(W / (2.0 * tanx));
    float fy = (float)(H / (2.0 * tany));

    prep_kernel<<<1, MAXN>>>(colors, opac, pos, scales, rots, wcoef, widx,
                             view, VP, N, fx, fy, (float)W, (float)H);

    dim3 blk(16, 8, 4);
    dim3 grd((W + 15) / 16, (H + 7) / 8);
    render_kernel<<<grd, blk>>>(bg, (float*)d_out, N, W, H);
}

// round 4
// speedup vs baseline: 3.3055x; 1.1385x over previous
#include <cuda_runtime.h>
#include <math.h>
#include <float.h>

#define MAXN 512
#define KWAVE 8

// ---------------- fused: per-block prep + tile cull + in-block depth sort + composite ----------------
__global__ void __launch_bounds__(512, 3)
fused_kernel(const float* __restrict__ colors,
             const float* __restrict__ opac,
             const float* __restrict__ bg,
             const float* __restrict__ pos,
             const float* __restrict__ scales,
             const float* __restrict__ rots,
             const float* __restrict__ wcoef,
             const int*   __restrict__ widx,
             const float* __restrict__ view,
             const float* __restrict__ VP,
             float* __restrict__ out,
             int N, int W, int H, float fx, float fy)
{
    __shared__ float4 s_rec[MAXN];   // px,py,r2,op (compacted)
    __shared__ float4 s_f1 [MAXN];   // conA,conB,conC,a2x
    __shared__ float4 s_f2 [MAXN];   // a2y,colR,colG,colB
    __shared__ float  s_dep[MAXN];   // depth of compacted records
    __shared__ short  s_ord[MAXN];   // primitive ids of compacted records
    __shared__ int    s_cnt[16];
    __shared__ int    s_total;
    __shared__ float4 s_acc[4][128]; // per-segment (cr,cg,cb,T)

    int tid  = (threadIdx.z * 8 + threadIdx.y) * 16 + threadIdx.x;
    int warp = tid >> 5;
    int lane = tid & 31;
    float Wf = (float)W, Hf = (float)H;

    // ---------- phase 0: per-thread primitive prep (prim = tid) ----------
    float depth = FLT_MAX;
    float4 rec = make_float4(0.f, 0.f, 0.f, 0.f);
    float4 rf1 = make_float4(0.f, 0.f, 0.f, 0.f);
    float4 rf2 = make_float4(0.f, 0.f, 0.f, 0.f);

    if (tid < N) {
        int i = tid;
        float q0 = rots[4*i+0], q1 = rots[4*i+1], q2 = rots[4*i+2], q3 = rots[4*i+3];
        float qn = sqrtf(q0*q0 + q1*q1 + q2*q2 + q3*q3) + 1e-8f;
        float r = q0/qn, x = q1/qn, y = q2/qn, z = q3/qn;
        float R00 = 1.f - 2.f*(y*y + z*z), R01 = 2.f*(x*y - r*z), R02 = 2.f*(x*z + r*y);
        float R10 = 2.f*(x*y + r*z), R11 = 1.f - 2.f*(x*x + z*z), R12 = 2.f*(y*z - r*x);
        float R20 = 2.f*(x*z - r*y), R21 = 2.f*(y*z + r*x), R22 = 1.f - 2.f*(x*x + y*y);

        float sx = expf(scales[3*i+0]); float sy = expf(scales[3*i+1]); float sz = expf(scales[3*i+2]);
        float s0 = sx*sx, s1 = sy*sy, s2 = sz*sz;

        float S00 = R00*R00*s0 + R01*R01*s1 + R02*R02*s2;
        float S01 = R00*R10*s0 + R01*R11*s1 + R02*R12*s2;
        float S02 = R00*R20*s0 + R01*R21*s1 + R02*R22*s2;
        float S11 = R10*R10*s0 + R11*R11*s1 + R12*R12*s2;
        float S12 = R10*R20*s0 + R11*R21*s1 + R12*R22*s2;
        float S22 = R20*R20*s0 + R21*R21*s1 + R22*R22*s2;

        float p0 = pos[3*i+0], p1 = pos[3*i+1], p2 = pos[3*i+2];

        float tx  = view[0]*p0 + view[1]*p1 + view[2]*p2  + view[3];
        float ty  = view[4]*p0 + view[5]*p1 + view[6]*p2  + view[7];
        float tzc = view[8]*p0 + view[9]*p1 + view[10]*p2 + view[11];

        float c0 = VP[0]*p0  + VP[1]*p1  + VP[2]*p2  + VP[3];
        float c1 = VP[4]*p0  + VP[5]*p1  + VP[6]*p2  + VP[7];
        float w  = VP[12]*p0 + VP[13]*p1 + VP[14]*p2 + VP[15];
        float wsafe = (fabsf(w) > 1e-6f) ? w : 1e-6f;
        float pxx = (c0/wsafe * 0.5f + 0.5f) * Wf;
        float pyy = (c1/wsafe * 0.5f + 0.5f) * Hf;

        depth = tzc;
        float tzm = fmaxf(depth, 0.1f);
        float inv = 1.0f / tzm;
        float J00 = fx*inv, J02 = -fx*tx*inv*inv;
        float J11 = fy*inv, J12 = -fy*ty*inv*inv;

        float M00 = J00*view[0] + J02*view[8];
        float M01 = J00*view[1] + J02*view[9];
        float M02 = J00*view[2] + J02*view[10];
        float M10 = J11*view[4] + J12*view[8];
        float M11 = J11*view[5] + J12*view[9];
        float M12 = J11*view[6] + J12*view[10];

        float t00 = M00*S00 + M01*S01 + M02*S02;
        float t01 = M00*S01 + M01*S11 + M02*S12;
        float t02 = M00*S02 + M01*S12 + M02*S22;
        float t10 = M10*S00 + M11*S01 + M12*S02;
        float t11 = M10*S01 + M11*S11 + M12*S12;
        float t12 = M10*S02 + M11*S12 + M12*S22;
        float cov00 = t00*M00 + t01*M01 + t02*M02;
        float cov01 = t00*M10 + t01*M11 + t02*M12;
        float cov11 = t10*M10 + t11*M11 + t12*M12;

        float A = cov00 + 0.3f, B = cov01, C = cov11 + 0.3f;
        float det = fmaxf(A*C - B*B, 1e-12f);
        float invd = 1.0f / det;
        float conA = C*invd, conB = -B*invd, conC = A*invd;

        float a2x = M00*R00 + M01*R10 + M02*R20;
        float a2y = M10*R00 + M11*R10 + M12*R20;
        float an = sqrtf(a2x*a2x + a2y*a2y) + 1e-8f;
        a2x /= an; a2y /= an;

        float op = opac[i];

        float maxw = 0.f;
        #pragma unroll
        for (int k = 0; k < KWAVE; k++) maxw += fabsf(wcoef[KWAVE*i + k]);

        bool valid = (depth > 0.1f) && (w > 1e-4f);

        float mean = 0.5f*(conA + conC);
        float lmin = mean - sqrtf(fmaxf(0.25f*(conA-conC)*(conA-conC) + conB*conB, 0.f));
        lmin = fmaxf(lmin, 1e-12f);
        float r2 = 0.f;
        float prod = op * maxw;
        if (valid && prod > 0.f) {
            float thr = logf(prod) + 18.4207f;   // ln(1e8)
            if (thr > 0.f) r2 = 2.f * thr / lmin;
        }

        rec = make_float4(pxx, pyy, r2, op);
        rf1 = make_float4(conA, conB, conC, a2x);
        rf2 = make_float4(a2y, colors[3*i+0], colors[3*i+1], colors[3*i+2]);
    }

    // ---------- phase 1: tile cull + order-preserving compaction ----------
    float xmin = (float)(blockIdx.x * 16) + 0.5f;
    float ymin = (float)(blockIdx.y * 8)  + 0.5f;
    float xmax = xmin + 15.0f;
    float ymax = ymin + 7.0f;

    float nx = fminf(fmaxf(rec.x, xmin), xmax);
    float ny = fminf(fmaxf(rec.y, ymin), ymax);
    float ddx = rec.x - nx, ddy = rec.y - ny;
    bool p = (ddx*ddx + ddy*ddy) < rec.z;     // NaN-safe: false

    unsigned msk = __ballot_sync(0xffffffffu, p);
    if (lane == 0) s_cnt[warp] = __popc(msk);
    __syncthreads();

    int pre = 0, run = 0;
    #pragma unroll
    for (int wv = 0; wv < 16; wv++) {
        int c = s_cnt[wv];
        if (wv < warp) pre += c;
        run += c;
    }
    if (tid == 0) s_total = run;

    if (p) {
        int off = pre + __popc(msk & ((1u << lane) - 1));
        s_rec[off] = rec;
        s_f1 [off] = rf1;
        s_f2 [off] = rf2;
        s_dep[off] = depth;
        s_ord[off] = (short)tid;
    }
    __syncthreads();
    int M = s_total;

    // ---------- phase 2: in-block bitonic sort of survivors by depth ----------
    {
        int P = 32; while (P < M) P <<= 1;
        float key = (tid < M) ? s_dep[tid] : FLT_MAX;
        int   val = tid;
        for (int k = 2; k <= P; k <<= 1) {
            bool up = ((tid & k) == 0);
            for (int j = k >> 1; j > 0; j >>= 1) {
                float okey; int oval;
                if (j >= 32) {
                    __syncthreads();
                    if (tid < P) { s_dep[tid] = key; ((int*)s_cnt, 0); }
                    // need a second buffer for vals: reuse s_acc as scratch
                    if (tid < P) { ((int*)s_acc)[tid] = val; }
                    __syncthreads();
                    okey = (tid < P) ? s_dep[tid ^ j] : key;
                    oval = (tid < P) ? ((int*)s_acc)[tid ^ j] : val;
                } else {
                    okey = __shfl_xor_sync(0xffffffffu, key, j);
                    oval = __shfl_xor_sync(0xffffffffu, val, j);
                }
                if (tid < P) {
                    bool lower = ((tid & j) == 0);
                    bool takeMin = (lower == up);
                    bool sw = takeMin ? (okey < key) : (okey > key);
                    if (sw) { key = okey; val = oval; }
                }
            }
        }
        // in-place permute: thread tid (rank) gathers record at slot val
        __syncthreads();
        float4 pr, pf1, pf2; short po = 0;
        if (tid < M) { pr = s_rec[val]; pf1 = s_f1[val]; pf2 = s_f2[val]; po = s_ord[val]; }
        __syncthreads();
        if (tid < M) { s_rec[tid] = pr; s_f1[tid] = pf1; s_f2[tid] = pf2; s_ord[tid] = po; }
        __syncthreads();
    }

    // ---------- phase 3: per-pixel composite over 4 depth segments ----------
    int x = blockIdx.x * 16 + threadIdx.x;
    int y = blockIdx.y * 8  + threadIdx.y;
    int seg = threadIdx.z;
    float gx = (float)x + 0.5f;
    float gy = (float)y + 0.5f;

    int m0 = (M * seg)     >> 2;
    int m1 = (M * (seg+1)) >> 2;

    const float omc = 0.785398163397448f / Wf;   // (pi/4)/W

    float T = 1.0f, cr = 0.f, cg = 0.f, cb = 0.f;

    for (int m = m0; m < m1; m++) {
        float4 c = s_rec[m];
        float dx = c.x - gx;
        float dy = c.y - gy;
        float d2 = dx*dx + dy*dy;
        if (d2 < c.z) {
            float4 f1 = s_f1[m];
            float4 f2 = s_f2[m];
            int o = (int)s_ord[m];
            float power = -0.5f*(f1.x*dx*dx + f1.z*dy*dy) - f1.y*dx*dy;
            float G = __expf(fminf(power, 0.f));
            float t = dx*f1.w + dy*f2.x;
            float4 wc0 = __ldg((const float4*)(wcoef + KWAVE*o));
            float4 wc1 = __ldg((const float4*)(wcoef + KWAVE*o) + 1);
            int4   wi0 = __ldg((const int4*)(widx + KWAVE*o));
            int4   wi1 = __ldg((const int4*)(widx + KWAVE*o) + 1);
            float ts = t * omc;
            float wave = wc0.x*__cosf((float)wi0.x*ts) + wc0.y*__cosf((float)wi0.y*ts)
                       + wc0.z*__cosf((float)wi0.z*ts) + wc0.w*__cosf((float)wi0.w*ts)
                       + wc1.x*__cosf((float)wi1.x*ts) + wc1.y*__cosf((float)wi1.y*ts)
                       + wc1.z*__cosf((float)wi1.z*ts) + wc1.w*__cosf((float)wi1.w*ts);
            float alpha = fminf(fmaxf(c.w * G * wave, 0.f), 0.99f);
            float wgt = alpha * T;
            cr += wgt * f2.y;
            cg += wgt * f2.z;
            cb += wgt * f2.w;
            T *= 1.0f - alpha;
        }
    }

    int pixl = threadIdx.y * 16 + threadIdx.x;
    s_acc[seg][pixl] = make_float4(cr, cg, cb, T);
    __syncthreads();

    if (seg == 0 && x < W && y < H) {
        float4 a0 = s_acc[0][pixl];
        float4 a1 = s_acc[1][pixl];
        float4 a2 = s_acc[2][pixl];
        float4 a3 = s_acc[3][pixl];
        float fr = a0.x + a0.w*(a1.x + a1.w*(a2.x + a2.w*a3.x));
        float fg = a0.y + a0.w*(a1.y + a1.w*(a2.y + a2.w*a3.y));
        float fb = a0.z + a0.w*(a1.z + a1.w*(a2.z + a2.w*a3.z));
        float fT = a0.w * a1.w * a2.w * a3.w;
        int pix = y*W + x;
        int HW = W*H;
        out[pix]        = fr + bg[0]*fT;
        out[HW + pix]   = fg + bg[1]*fT;
        out[2*HW + pix] = fb + bg[2]*fT;
    }
}

// ---------------- launch ----------------
extern "C" void kernel_launch(void* const* d_in, const int* in_sizes, int n_in,
                              void* d_out, int out_size)
{
    const float* colors = (const float*)d_in[0];
    const float* opac   = (const float*)d_in[1];
    const float* bg     = (const float*)d_in[2];
    const float* pos    = (const float*)d_in[3];
    const float* scales = (const float*)d_in[4];
    const float* rots   = (const float*)d_in[5];
    const float* wcoef  = (const float*)d_in[6];
    const int*   widx   = (const int*)d_in[7];
    const float* view   = (const float*)d_in[9];
    const float* VP     = (const float*)d_in[10];

    int N = in_sizes[3] / 3;
    if (N > MAXN) N = MAXN;

    int HW = out_size / 3;
    int W = 200, H = 200;
    if (HW != 40000) {
        W = (int)(sqrt((double)HW) + 0.5);
        H = (W > 0) ? HW / W : 0;
    }

    const double tanx = tan(30.0 * M_PI / 180.0);  // FOV 60 deg
    const double tany = tan(30.0 * M_PI / 180.0);
    float fx = (float)(W / (2.0 * tanx));
    float fy = (float)(H / (2.0 * tany));

    dim3 blk(16, 8, 4);
    dim3 grd((W + 15) / 16, (H + 7) / 8);
    fused_kernel<<<grd, blk>>>(colors, opac, bg, pos, scales, rots, wcoef, widx,
                               view, VP, (float*)d_out, N, W, H, fx, fy);
}